// round 11
// baseline (speedup 1.0000x reference)
#include <cuda_runtime.h>
#include <cstdint>
#include <math.h>

// ---------------- problem constants ----------------
#define N_PTS   65536            // 16 * 64 * 64 points
#define KCODES  1024
#define DIM     64
#define NELEM   4194304          // 16*64*64*64
#define HW      4096             // 64*64

// output layout: loss | quantized_st (NCHW) | perplexity | encodings [N, K]
#define OFF_LOSS 0
#define OFF_Q    1
#define OFF_PERP (1 + NELEM)
#define OFF_ENC  (OFF_PERP + 1)

// ---------------- schedule ----------------
#define GRID      304            // 2 blocks/SM x 152 SMs, work-stealing tickets
#define NTHR      256
#define TILE_PTS  128
#define NTILES    (N_PTS / TILE_PTS)   // 512
#define KT        128
#define NKT       (KCODES / KT)        // 8

// ---------------- smem layout (bytes) ----------------
#define SM_X    0                // 64 d x 128 pts floats       (32768)
#define SM_W    32768            // 2 x (64 d x 128 c) floats   (65536)
#define SM_WN   98304            // 2 x 128 floats              (1024)
#define SM_S1   99328            // 128 floats                  (512)
#define SM_BI   99840            // 128 ints                    (512)
#define SM_RS   100352           // 8 warps x 128 floats        (4096)
#define SM_RI   104448           // 8 warps x 128 ints          (4096)
#define SM_TOT  108544

// ---------------- device scratch ----------------
__device__ __align__(16) float g_wt[DIM * KCODES];   // wt[d*1024 + k]
__device__ __align__(16) float g_wnorm[KCODES];
__device__ float g_loss_sum;
__device__ int   g_hist[KCODES];
__device__ int   g_done;
__device__ int   g_ticket;

// ---------------- helpers ----------------
__device__ __forceinline__ unsigned long long pack2(float v) {
    unsigned long long r;
    asm("mov.b64 %0, {%1, %1};" : "=l"(r) : "f"(v));
    return r;
}
__device__ __forceinline__ unsigned long long fma2(unsigned long long a,
                                                   unsigned long long b,
                                                   unsigned long long c) {
    unsigned long long d;
    asm("fma.rn.f32x2 %0, %1, %2, %3;" : "=l"(d) : "l"(a), "l"(b), "l"(c));
    return d;
}
__device__ __forceinline__ void unpack2(unsigned long long v, float& lo, float& hi) {
    asm("mov.b64 {%0, %1}, %2;" : "=f"(lo), "=f"(hi) : "l"(v));
}
__device__ __forceinline__ void cp16(uint32_t dst_smem, const void* src) {
    asm volatile("cp.async.cg.shared.global [%0], [%1], 16;" :: "r"(dst_smem), "l"(src));
}
__device__ __forceinline__ void cp_commit() { asm volatile("cp.async.commit_group;"); }
__device__ __forceinline__ void cp_wait0()  { asm volatile("cp.async.wait_group 0;"); }

// ============================================================================
// K0: transpose W -> g_wt[d][k], s2[k] via sequential fp32 mul/add (reference
// rounding emulation), reset accumulators/tickets.  grid: 8 x 128
// ============================================================================
__global__ void k0_prep(const float* __restrict__ W) {
    int k = blockIdx.x * 128 + threadIdx.x;      // 0..1023
    if (blockIdx.x == 0 && threadIdx.x == 0) {
        g_loss_sum = 0.0f; g_done = 0; g_ticket = 0;
    }
    g_hist[k] = 0;
    float nrm = 0.0f;
    const float4* wr = reinterpret_cast<const float4*>(W + k * DIM);
#pragma unroll
    for (int i = 0; i < 16; i++) {
        float4 v = wr[i];
        nrm = __fadd_rn(nrm, __fmul_rn(v.x, v.x));
        nrm = __fadd_rn(nrm, __fmul_rn(v.y, v.y));
        nrm = __fadd_rn(nrm, __fmul_rn(v.z, v.z));
        nrm = __fadd_rn(nrm, __fmul_rn(v.w, v.w));
        g_wt[(i * 4 + 0) * KCODES + k] = v.x;
        g_wt[(i * 4 + 1) * KCODES + k] = v.y;
        g_wt[(i * 4 + 2) * KCODES + k] = v.z;
        g_wt[(i * 4 + 3) * KCODES + k] = v.w;
    }
    g_wnorm[k] = nrm;
}

// ============================================================================
// K1: persistent fused kernel, 256 thr/block, 2 blocks/SM (4 warps/SMSP).
// Thread tile: 16 pts (pg = tid&7, slots {i*8+pg}, conflict-free)
//            x 4 codes (ct = tid>>3, 32 cts x 4 = 128 codes = KT).
// Per thread-d: 4 LDS.128 (x) + 1 LDS.128 (w) + 4 packs + 32 fma2.
// ============================================================================
extern __shared__ char smem_raw[];

__global__ void __launch_bounds__(NTHR, 2) k1_main(const float* __restrict__ X,
                                                   const float* __restrict__ Wp,
                                                   float* __restrict__ out) {
    const int tid  = threadIdx.x;
    const int pg   = tid & 7;                    // 8 pt-groups x 16 pts
    const int ct   = tid >> 3;                   // 32 code-threads x 4 codes
    const int lane = tid & 31;
    const int wrp  = tid >> 5;                   // 8 warps

    const float* xsf  = reinterpret_cast<const float*>(smem_raw + SM_X);
    float4*      x4s  = reinterpret_cast<float4*>(smem_raw + SM_X);
    const float* wnf  = reinterpret_cast<const float*>(smem_raw + SM_WN);
    float*       s1sm = reinterpret_cast<float*>(smem_raw + SM_S1);
    int*         bidx_sm = reinterpret_cast<int*>(smem_raw + SM_BI);
    float*       red_s = reinterpret_cast<float*>(smem_raw + SM_RS);
    int*         red_i = reinterpret_cast<int*>  (smem_raw + SM_RI);

    uint32_t smem_base = (uint32_t)__cvta_generic_to_shared(smem_raw);
    uint32_t w_sm  = smem_base + SM_W;
    uint32_t wn_sm = smem_base + SM_WN;

    __shared__ int tsm;
    float ls_acc = 0.0f;

    for (;;) {
        __syncthreads();                          // smem reuse + ticket barrier
        if (tid == 0) tsm = atomicAdd(&g_ticket, 1);
        __syncthreads();
        const int t = tsm;
        if (t >= NTILES) break;

        const int n0  = t * TILE_PTS;
        const int b   = n0 >> 12;
        const int hw0 = n0 & 4095;

        // prefetch W k-tile 0 -> buffer 0 (8 cp16/thread) + wn
#pragma unroll
        for (int i = 0; i < 8; i++) {
            int lin = i * NTHR + tid;            // 0..2047
            int d = lin >> 5, seg = lin & 31;
            cp16(w_sm + d * 512 + seg * 16, g_wt + d * KCODES + seg * 4);
        }
        if (tid < 32) cp16(wn_sm + tid * 16, g_wnorm + tid * 4);
        cp_commit();

        // load x tile (64 d x 128 pts), raw layout x[d][p]
        {
            int j = tid & 31, d0 = tid >> 5;     // j: float4 over pts, d0: 0..7
            const float* xb = X + (size_t)b * (DIM * HW) + hw0;
#pragma unroll
            for (int i = 0; i < 8; i++) {
                int d = d0 + i * 8;
                x4s[d * 32 + j] =
                    *reinterpret_cast<const float4*>(xb + (size_t)d * HW + j * 4);
            }
        }
        __syncthreads();

        // s1[p]: sequential fp32 mul/add over d ascending (reference emulation)
        if (tid < 128) {
            float s1 = 0.0f;
#pragma unroll
            for (int d = 0; d < DIM; d++) {
                float xv = xsf[d * 128 + tid];
                s1 = __fadd_rn(s1, __fmul_rn(xv, xv));
            }
            s1sm[tid] = s1;
        }
        cp_wait0();
        __syncthreads();

        float best[16];
        int   bidx[16];
#pragma unroll
        for (int p = 0; p < 16; p++) { best[p] = 3.4e38f; bidx[p] = 0; }

        for (int kt = 0; kt < NKT; kt++) {
            const int buf = kt & 1;
            if (kt + 1 < NKT) {
                const int kb = (kt + 1) * KT;
                const int nb = buf ^ 1;
#pragma unroll
                for (int i = 0; i < 8; i++) {
                    int lin = i * NTHR + tid;
                    int d = lin >> 5, seg = lin & 31;
                    cp16(w_sm + nb * 32768 + d * 512 + seg * 16,
                         g_wt + d * KCODES + kb + seg * 4);
                }
                if (tid < 32) cp16(wn_sm + nb * 512 + tid * 16, g_wnorm + kb + tid * 4);
                cp_commit();
            }

            // zero-fill this tile's slice of encodings (overlaps FMA on DRAM)
            // encodings region is only 8B-aligned -> float2 is the widest store.
            {
                float2 z; z.x = 0.0f; z.y = 0.0f;
                float2* enc2 =
                    reinterpret_cast<float2*>(out + OFF_ENC) + (size_t)n0 * 512;
                int base = kt * 8192 + tid;
#pragma unroll
                for (int s = 0; s < 32; s++) enc2[base + s * 256] = z;
            }

            // ---- GEMM: acc[pair-half(8)][code(4)], f32x2 lanes = 2 points ----
            unsigned long long acc[8][4];
#pragma unroll
            for (int m = 0; m < 8; m++)
#pragma unroll
                for (int c = 0; c < 4; c++) acc[m][c] = 0ull;

            const ulonglong2* x2 =
                reinterpret_cast<const ulonglong2*>(smem_raw + SM_X);
            const float4* wf4 =
                reinterpret_cast<const float4*>(smem_raw + SM_W + buf * 32768);

#pragma unroll 2
            for (int d = 0; d < DIM; d++) {
                ulonglong2 xv[4];
#pragma unroll
                for (int i = 0; i < 4; i++) xv[i] = x2[d * 32 + i * 8 + pg];
                float4 wq0 = wf4[d * 32 + ct];
                unsigned long long wv[4];
                wv[0] = pack2(wq0.x); wv[1] = pack2(wq0.y);
                wv[2] = pack2(wq0.z); wv[3] = pack2(wq0.w);
#pragma unroll
                for (int c = 0; c < 4; c++) {
                    acc[0][c] = fma2(xv[0].x, wv[c], acc[0][c]);
                    acc[1][c] = fma2(xv[0].y, wv[c], acc[1][c]);
                    acc[2][c] = fma2(xv[1].x, wv[c], acc[2][c]);
                    acc[3][c] = fma2(xv[1].y, wv[c], acc[3][c]);
                    acc[4][c] = fma2(xv[2].x, wv[c], acc[4][c]);
                    acc[5][c] = fma2(xv[2].y, wv[c], acc[5][c]);
                    acc[6][c] = fma2(xv[3].x, wv[c], acc[6][c]);
                    acc[7][c] = fma2(xv[3].y, wv[c], acc[7][c]);
                }
            }

            // d = fsub(fadd(s1, s2), 2*dot) — reference rounding; strict-< argmin
            // acc[m][*]: pair pm = (m>>1)*8 + pg, sub-pair (m&1)
            //            -> points Pm = 4*((m>>1)*8 + pg) + 2*(m&1), Pm+1
            const int kbase = kt * KT + ct * 4;
#pragma unroll
            for (int m = 0; m < 8; m++) {
                const int Pm = 4 * ((m >> 1) * 8 + pg) + 2 * (m & 1);
                float s1lo = s1sm[Pm];
                float s1hi = s1sm[Pm + 1];
#pragma unroll
                for (int c = 0; c < 4; c++) {
                    float lo, hi; unpack2(acc[m][c], lo, hi);
                    float wn = wnf[buf * 128 + ct * 4 + c];
                    float e0 = __fsub_rn(__fadd_rn(s1lo, wn), __fmul_rn(2.0f, lo));
                    float e1 = __fsub_rn(__fadd_rn(s1hi, wn), __fmul_rn(2.0f, hi));
                    if (e0 < best[2 * m])     { best[2 * m]     = e0; bidx[2 * m]     = kbase + c; }
                    if (e1 < best[2 * m + 1]) { best[2 * m + 1] = e1; bidx[2 * m + 1] = kbase + c; }
                }
            }

            if (kt + 1 < NKT) cp_wait0();
            __syncthreads();
        }

        // intra-warp reduction across the 4 in-warp ct values (stride-8 lanes)
#pragma unroll
        for (int p = 0; p < 16; p++) {
            float bs = best[p];
            int   bi = bidx[p];
#pragma unroll
            for (int off = 8; off < 32; off <<= 1) {
                float os = __shfl_xor_sync(0xffffffffu, bs, off);
                int   oi = __shfl_xor_sync(0xffffffffu, bi, off);
                if (os < bs || (os == bs && oi < bi)) { bs = os; bi = oi; }
            }
            best[p] = bs; bidx[p] = bi;
        }
        if (lane < 8) {
            // local index p -> point 32*(p>>2) + 4*pg + (p&3)
#pragma unroll
            for (int p = 0; p < 16; p++) {
                int pt = 32 * (p >> 2) + 4 * pg + (p & 3);
                red_s[wrp * 128 + pt] = best[p];
                red_i[wrp * 128 + pt] = bidx[p];
            }
        }
        __syncthreads();
        if (tid < 128) {
            // point n = tid
            float bs = red_s[tid];
            int   bi = red_i[tid];
#pragma unroll
            for (int w = 1; w < 8; w++) {
                float s = red_s[w * 128 + tid];
                int   i2 = red_i[w * 128 + tid];
                if (s < bs || (s == bs && i2 < bi)) { bs = s; bi = i2; }
            }
            bidx_sm[tid] = bi;
            atomicAdd(&g_hist[bi], 1);
            // zero-fill of this row finished in kt loop; barrier orders it
            out[(size_t)OFF_ENC + (size_t)(n0 + tid) * KCODES + bi] = 1.0f;
        }
        __syncthreads();

        // quantized_st = fadd(x, fsub(q, x)) (reference STE rounding) + loss
        {
            int p = tid & 127, half = tid >> 7;  // 2 threads per point
            int bi = bidx_sm[p];
            const float4* wrow =
                reinterpret_cast<const float4*>(Wp + bi * DIM) + half * 8;
            float* oq = out + OFF_Q + (size_t)b * (DIM * HW) + hw0 + p;
#pragma unroll
            for (int i = 0; i < 8; i++) {
                float4 qv = __ldg(wrow + i);
                int c0 = half * 32 + i * 4;
                float x0 = xsf[(c0 + 0) * 128 + p];
                float x1 = xsf[(c0 + 1) * 128 + p];
                float x2v = xsf[(c0 + 2) * 128 + p];
                float x3 = xsf[(c0 + 3) * 128 + p];
                float d0 = __fsub_rn(qv.x, x0);
                float d1 = __fsub_rn(qv.y, x1);
                float d2 = __fsub_rn(qv.z, x2v);
                float d3 = __fsub_rn(qv.w, x3);
                oq[(size_t)(c0 + 0) * HW] = __fadd_rn(x0, d0);
                oq[(size_t)(c0 + 1) * HW] = __fadd_rn(x1, d1);
                oq[(size_t)(c0 + 2) * HW] = __fadd_rn(x2v, d2);
                oq[(size_t)(c0 + 3) * HW] = __fadd_rn(x3, d3);
                ls_acc += d0 * d0 + d1 * d1 + d2 * d2 + d3 * d3;
            }
        }
    }

    // ---- block loss reduce + completion ticket ----
    __shared__ float wsum[8];
    __shared__ int is_last;
#pragma unroll
    for (int s = 16; s > 0; s >>= 1) ls_acc += __shfl_xor_sync(0xffffffffu, ls_acc, s);
    if (lane == 0) wsum[wrp] = ls_acc;
    __syncthreads();
    if (tid == 0) {
        float s = 0.0f;
#pragma unroll
        for (int w = 0; w < 8; w++) s += wsum[w];
        atomicAdd(&g_loss_sum, s);
        __threadfence();
        is_last = (atomicAdd(&g_done, 1) == GRID - 1) ? 1 : 0;
    }
    __syncthreads();

    if (is_last) {
        float v = 0.0f;
#pragma unroll
        for (int i = 0; i < 4; i++) {
            int c = tid + NTHR * i;
            float p = (float)__ldcg(&g_hist[c]) * (1.0f / (float)N_PTS);
            v += p * logf(p + 1e-10f);
        }
#pragma unroll
        for (int s = 16; s > 0; s >>= 1) v += __shfl_xor_sync(0xffffffffu, v, s);
        __shared__ float fin[8];
        if (lane == 0) fin[wrp] = v;
        __syncthreads();
        if (tid == 0) {
            float s = 0.0f;
#pragma unroll
            for (int w = 0; w < 8; w++) s += fin[w];
            out[OFF_PERP] = expf(-s);
            out[OFF_LOSS] = 1.25f * __ldcg(&g_loss_sum) * (1.0f / (float)NELEM);
        }
    }
}

// ============================================================================
extern "C" void kernel_launch(void* const* d_in, const int* in_sizes, int n_in,
                              void* d_out, int out_size) {
    const float* X = (const float*)d_in[0];
    const float* W = (const float*)d_in[1];
    if (n_in >= 2 && in_sizes[0] == KCODES * DIM && in_sizes[1] == NELEM) {
        const float* t = X; X = W; W = t;   // defensive order swap
    }
    float* out = (float*)d_out;

    cudaFuncSetAttribute(k1_main, cudaFuncAttributeMaxDynamicSharedMemorySize, SM_TOT);

    k0_prep<<<8, 128>>>(W);
    k1_main<<<GRID, NTHR, SM_TOT>>>(X, W, out);
}

// round 13
// speedup vs baseline: 1.2347x; 1.2347x over previous
#include <cuda_runtime.h>
#include <cstdint>
#include <math.h>

// ---------------- problem constants ----------------
#define N_PTS   65536            // 16 * 64 * 64 points
#define KCODES  1024
#define DIM     64
#define NELEM   4194304          // 16*64*64*64
#define HW      4096             // 64*64

// output layout: loss | quantized_st (NCHW) | perplexity | encodings [N, K]
#define OFF_LOSS 0
#define OFF_Q    1
#define OFF_PERP (1 + NELEM)
#define OFF_ENC  (OFF_PERP + 1)

// ---------------- schedule ----------------
#define GRID      456            // 3 blocks/SM x 152 SMs, work-stealing tickets
#define NTHR      128
#define TILE_PTS  32
#define NTILES    (N_PTS / TILE_PTS)   // 2048
#define KT        256
#define NKT       (KCODES / KT)        // 4

// ---------------- smem layout (bytes) ----------------
#define SM_X    0                // 64 d x 32 pts floats        (8192)
#define SM_WN   8192             // 1024 floats (s2, loaded once) (4096)
#define SM_S1   12288            // 32 floats                   (128)
#define SM_BI   12416            // 32 ints                     (128)
#define SM_RS   12544            // 4 warps x 32 floats         (512)
#define SM_RI   13056            // 4 warps x 32 ints           (512)
#define SM_TOT  13568

// ---------------- device scratch ----------------
__device__ __align__(16) float g_wt[DIM * KCODES];   // wt[d*1024 + k]
__device__ __align__(16) float g_wnorm[KCODES];
__device__ float g_loss_sum;
__device__ int   g_hist[KCODES];
__device__ int   g_done;
__device__ int   g_ticket;

// ---------------- helpers ----------------
__device__ __forceinline__ unsigned long long pack2(float v) {
    unsigned long long r;
    asm("mov.b64 %0, {%1, %1};" : "=l"(r) : "f"(v));
    return r;
}
__device__ __forceinline__ unsigned long long fma2(unsigned long long a,
                                                   unsigned long long b,
                                                   unsigned long long c) {
    unsigned long long d;
    asm("fma.rn.f32x2 %0, %1, %2, %3;" : "=l"(d) : "l"(a), "l"(b), "l"(c));
    return d;
}
__device__ __forceinline__ void unpack2(unsigned long long v, float& lo, float& hi) {
    asm("mov.b64 {%0, %1}, %2;" : "=f"(lo), "=f"(hi) : "l"(v));
}

// ============================================================================
// K0: transpose W -> g_wt[d][k], s2[k] via sequential fp32 mul/add (reference
// rounding emulation), reset accumulators/tickets.  grid: 8 x 128
// ============================================================================
__global__ void k0_prep(const float* __restrict__ W) {
    int k = blockIdx.x * 128 + threadIdx.x;      // 0..1023
    if (blockIdx.x == 0 && threadIdx.x == 0) {
        g_loss_sum = 0.0f; g_done = 0; g_ticket = 0;
    }
    g_hist[k] = 0;
    float nrm = 0.0f;
    const float4* wr = reinterpret_cast<const float4*>(W + k * DIM);
#pragma unroll
    for (int i = 0; i < 16; i++) {
        float4 v = wr[i];
        nrm = __fadd_rn(nrm, __fmul_rn(v.x, v.x));
        nrm = __fadd_rn(nrm, __fmul_rn(v.y, v.y));
        nrm = __fadd_rn(nrm, __fmul_rn(v.z, v.z));
        nrm = __fadd_rn(nrm, __fmul_rn(v.w, v.w));
        g_wt[(i * 4 + 0) * KCODES + k] = v.x;
        g_wt[(i * 4 + 1) * KCODES + k] = v.y;
        g_wt[(i * 4 + 2) * KCODES + k] = v.z;
        g_wt[(i * 4 + 3) * KCODES + k] = v.w;
    }
    g_wnorm[k] = nrm;
}

// ============================================================================
// K1: persistent fused kernel, 3 blocks/SM, W streamed from L2 via LDG
// (no smem W, no cp.async, no per-kt barriers). Tiles of 32 points.
// Thread tile: 8 pts (pg = tid&3) x 8 codes (ct = tid>>2, 32 cts x 8 = 256 = KT).
// x pairs at ulonglong2 slots {pg} and {4+pg} -> conflict-free LDS.128.
// Thread pts: {4pg..4pg+3} u {16+4pg..16+4pg+3}.
// ============================================================================
extern __shared__ char smem_raw[];

__global__ void __launch_bounds__(NTHR, 3) k1_main(const float* __restrict__ X,
                                                   const float* __restrict__ Wp,
                                                   float* __restrict__ out) {
    const int tid  = threadIdx.x;
    const int pg   = tid & 3;                    // 4 pt-groups x 8 pts = 32
    const int ct   = tid >> 2;                   // 32 code-threads x 8 codes
    const int lane = tid & 31;
    const int wrp  = tid >> 5;                   // 4 warps

    const float* xsf  = reinterpret_cast<const float*>(smem_raw + SM_X);
    float4*      x4s  = reinterpret_cast<float4*>(smem_raw + SM_X);
    float*       wnsm = reinterpret_cast<float*>(smem_raw + SM_WN);
    float*       s1sm = reinterpret_cast<float*>(smem_raw + SM_S1);
    int*         bidx_sm = reinterpret_cast<int*>(smem_raw + SM_BI);
    float*       red_s = reinterpret_cast<float*>(smem_raw + SM_RS);
    int*         red_i = reinterpret_cast<int*>  (smem_raw + SM_RI);

    // stage s2 (w norms) into smem once — constant across all tiles
    for (int i = tid; i < KCODES; i += NTHR) wnsm[i] = g_wnorm[i];

    __shared__ int tsm;
    float ls_acc = 0.0f;

    for (;;) {
        __syncthreads();                          // smem reuse + ticket barrier
        if (tid == 0) tsm = atomicAdd(&g_ticket, 1);
        __syncthreads();
        const int t = tsm;
        if (t >= NTILES) break;

        const int n0  = t * TILE_PTS;
        const int b   = n0 >> 12;
        const int hw0 = n0 & 4095;

        // load x tile (64 d x 32 pts), raw layout x[d][p]
        {
            int j = tid & 7, d0 = tid >> 3;      // j: float4 over pts, d0: 0..15
            const float* xb = X + (size_t)b * (DIM * HW) + hw0;
#pragma unroll
            for (int i = 0; i < 4; i++) {
                int d = d0 + i * 16;
                x4s[d * 8 + j] =
                    *reinterpret_cast<const float4*>(xb + (size_t)d * HW + j * 4);
            }
        }
        __syncthreads();

        // s1[p]: sequential fp32 mul/add over d ascending (reference emulation)
        if (tid < 32) {
            float s1 = 0.0f;
#pragma unroll
            for (int d = 0; d < DIM; d++) {
                float xv = xsf[d * 32 + tid];
                s1 = __fadd_rn(s1, __fmul_rn(xv, xv));
            }
            s1sm[tid] = s1;
        }
        __syncthreads();

        float best[8];
        int   bidx[8];
#pragma unroll
        for (int p = 0; p < 8; p++) { best[p] = 3.4e38f; bidx[p] = 0; }

#pragma unroll
        for (int kt = 0; kt < NKT; kt++) {
            // zero-fill this tile's slice of encodings (overlaps FMA on DRAM)
            // region is only 8B-aligned -> float2 stores.
            {
                float2 z; z.x = 0.0f; z.y = 0.0f;
                float2* enc2 =
                    reinterpret_cast<float2*>(out + OFF_ENC) + (size_t)n0 * 512;
                int base = kt * 4096 + tid;
#pragma unroll
                for (int s = 0; s < 32; s++) enc2[base + s * 128] = z;
            }

            // ---- GEMM: acc[pair(4)][code(8)], w streamed from L2 ----
            unsigned long long acc[4][8];
#pragma unroll
            for (int m = 0; m < 4; m++)
#pragma unroll
                for (int c = 0; c < 8; c++) acc[m][c] = 0ull;

            const ulonglong2* x2 =
                reinterpret_cast<const ulonglong2*>(smem_raw + SM_X);
            const float* wg = g_wt + kt * KT + ct * 8;

#pragma unroll 4
            for (int d = 0; d < DIM; d++) {
                ulonglong2 A = x2[d * 8 + pg];        // pts 4pg..4pg+3
                ulonglong2 B = x2[d * 8 + 4 + pg];    // pts 16+4pg..16+4pg+3
                float4 wq0 = __ldg(reinterpret_cast<const float4*>(wg + (size_t)d * KCODES));
                float4 wq1 = __ldg(reinterpret_cast<const float4*>(wg + (size_t)d * KCODES + 4));
                unsigned long long wv[8];
                wv[0] = pack2(wq0.x); wv[1] = pack2(wq0.y);
                wv[2] = pack2(wq0.z); wv[3] = pack2(wq0.w);
                wv[4] = pack2(wq1.x); wv[5] = pack2(wq1.y);
                wv[6] = pack2(wq1.z); wv[7] = pack2(wq1.w);
#pragma unroll
                for (int c = 0; c < 8; c++) {
                    acc[0][c] = fma2(A.x, wv[c], acc[0][c]);
                    acc[1][c] = fma2(A.y, wv[c], acc[1][c]);
                    acc[2][c] = fma2(B.x, wv[c], acc[2][c]);
                    acc[3][c] = fma2(B.y, wv[c], acc[3][c]);
                }
            }

            // d = fsub(fadd(s1, s2), 2*dot) — reference rounding; strict-< argmin
            // acc[m][*]: points Pm, Pm+1 with
            //   Pm = (m<2 ? 4*pg + 2*m : 16 + 4*pg + 2*(m-2))
            const int kbase = kt * KT + ct * 8;
#pragma unroll
            for (int m = 0; m < 4; m++) {
                const int Pm = (m < 2) ? (4 * pg + 2 * m) : (16 + 4 * pg + 2 * (m - 2));
                float s1lo = s1sm[Pm];
                float s1hi = s1sm[Pm + 1];
#pragma unroll
                for (int c = 0; c < 8; c++) {
                    float lo, hi; unpack2(acc[m][c], lo, hi);
                    float wn = wnsm[kbase + c];
                    float e0 = __fsub_rn(__fadd_rn(s1lo, wn), __fmul_rn(2.0f, lo));
                    float e1 = __fsub_rn(__fadd_rn(s1hi, wn), __fmul_rn(2.0f, hi));
                    if (e0 < best[2 * m])     { best[2 * m]     = e0; bidx[2 * m]     = kbase + c; }
                    if (e1 < best[2 * m + 1]) { best[2 * m + 1] = e1; bidx[2 * m + 1] = kbase + c; }
                }
            }
        }

        // intra-warp reduction across the 8 in-warp ct values (stride-4 lanes)
#pragma unroll
        for (int p = 0; p < 8; p++) {
            float bs = best[p];
            int   bi = bidx[p];
#pragma unroll
            for (int off = 4; off < 32; off <<= 1) {
                float os = __shfl_xor_sync(0xffffffffu, bs, off);
                int   oi = __shfl_xor_sync(0xffffffffu, bi, off);
                if (os < bs || (os == bs && oi < bi)) { bs = os; bi = oi; }
            }
            best[p] = bs; bidx[p] = bi;
        }
        if (lane < 4) {
            // local index p -> point (p<4 ? 4pg+p : 16+4pg+(p-4))
#pragma unroll
            for (int p = 0; p < 8; p++) {
                int pt = (p < 4) ? (4 * pg + p) : (16 + 4 * pg + (p - 4));
                red_s[wrp * 32 + pt] = best[p];
                red_i[wrp * 32 + pt] = bidx[p];
            }
        }
        __syncthreads();
        if (tid < 32) {
            // point n = tid
            float bs = red_s[tid];
            int   bi = red_i[tid];
#pragma unroll
            for (int w = 1; w < 4; w++) {
                float s = red_s[w * 32 + tid];
                int   i2 = red_i[w * 32 + tid];
                if (s < bs || (s == bs && i2 < bi)) { bs = s; bi = i2; }
            }
            bidx_sm[tid] = bi;
            atomicAdd(&g_hist[bi], 1);
            // zero-fill of this row finished in kt loop; barrier above orders it
            out[(size_t)OFF_ENC + (size_t)(n0 + tid) * KCODES + bi] = 1.0f;
        }
        __syncthreads();

        // quantized_st = fadd(x, fsub(q, x)) (reference STE rounding) + loss
        {
            int p = tid & 31, quarter = tid >> 5;  // 4 threads per point
            int bi = bidx_sm[p];
            const float4* wrow =
                reinterpret_cast<const float4*>(Wp + bi * DIM) + quarter * 4;
            float* oq = out + OFF_Q + (size_t)b * (DIM * HW) + hw0 + p;
#pragma unroll
            for (int i = 0; i < 4; i++) {
                float4 qv = __ldg(wrow + i);
                int c0 = quarter * 16 + i * 4;
                float x0 = xsf[(c0 + 0) * 32 + p];
                float x1 = xsf[(c0 + 1) * 32 + p];
                float x2v = xsf[(c0 + 2) * 32 + p];
                float x3 = xsf[(c0 + 3) * 32 + p];
                float d0 = __fsub_rn(qv.x, x0);
                float d1 = __fsub_rn(qv.y, x1);
                float d2 = __fsub_rn(qv.z, x2v);
                float d3 = __fsub_rn(qv.w, x3);
                oq[(size_t)(c0 + 0) * HW] = __fadd_rn(x0, d0);
                oq[(size_t)(c0 + 1) * HW] = __fadd_rn(x1, d1);
                oq[(size_t)(c0 + 2) * HW] = __fadd_rn(x2v, d2);
                oq[(size_t)(c0 + 3) * HW] = __fadd_rn(x3, d3);
                ls_acc += d0 * d0 + d1 * d1 + d2 * d2 + d3 * d3;
            }
        }
    }

    // ---- block loss reduce + completion ticket ----
    __shared__ float wsum[4];
    __shared__ int is_last;
#pragma unroll
    for (int s = 16; s > 0; s >>= 1) ls_acc += __shfl_xor_sync(0xffffffffu, ls_acc, s);
    if (lane == 0) wsum[wrp] = ls_acc;
    __syncthreads();
    if (tid == 0) {
        float s = wsum[0] + wsum[1] + wsum[2] + wsum[3];
        atomicAdd(&g_loss_sum, s);
        __threadfence();
        is_last = (atomicAdd(&g_done, 1) == GRID - 1) ? 1 : 0;
    }
    __syncthreads();

    if (is_last) {
        float v = 0.0f;
#pragma unroll
        for (int i = 0; i < 8; i++) {
            int c = tid + NTHR * i;
            float p = (float)__ldcg(&g_hist[c]) * (1.0f / (float)N_PTS);
            v += p * logf(p + 1e-10f);
        }
#pragma unroll
        for (int s = 16; s > 0; s >>= 1) v += __shfl_xor_sync(0xffffffffu, v, s);
        __shared__ float fin[4];
        if (lane == 0) fin[wrp] = v;
        __syncthreads();
        if (tid == 0) {
            float s = fin[0] + fin[1] + fin[2] + fin[3];
            out[OFF_PERP] = expf(-s);
            out[OFF_LOSS] = 1.25f * __ldcg(&g_loss_sum) * (1.0f / (float)NELEM);
        }
    }
}

// ============================================================================
extern "C" void kernel_launch(void* const* d_in, const int* in_sizes, int n_in,
                              void* d_out, int out_size) {
    const float* X = (const float*)d_in[0];
    const float* W = (const float*)d_in[1];
    if (n_in >= 2 && in_sizes[0] == KCODES * DIM && in_sizes[1] == NELEM) {
        const float* t = X; X = W; W = t;   // defensive order swap
    }
    float* out = (float*)d_out;

    cudaFuncSetAttribute(k1_main, cudaFuncAttributeMaxDynamicSharedMemorySize, SM_TOT);

    k0_prep<<<8, 128>>>(W);
    k1_main<<<GRID, NTHR, SM_TOT>>>(X, W, out);
}